// round 5
// baseline (speedup 1.0000x reference)
#include <cuda_runtime.h>
#include <math.h>

// ---------------- problem constants ----------------
#define N_ROWS 8192
#define DIM    128
#define NCLS   1000
#define EPSL   1e-10
// NCE temperature 0.1 -> multiply shifted cos by 10

// ---------------- scratch (device globals; no allocations allowed) ----------
__device__ float g_f1[N_ROWS * DIM];   // normalized fs
__device__ float g_f2[N_ROWS * DIM];   // normalized ft

#define NCHUNK 4
__device__ float g_part[NCHUNK * N_ROWS * 3];  // per-chunk (S1,S2,S3) partials
__device__ float g_S[N_ROWS * 3];              // combined S1,S2,S3 per row
__device__ float g_pos[N_ROWS * 4];            // L, P1, P2, P3 per row
__device__ int   g_npos[N_ROWS];
__device__ float g_jsd[N_ROWS];

// ---------------- K1: L2-normalize rows of fs, ft (warp per row) ------------
__global__ void k_normalize(const float* __restrict__ fs,
                            const float* __restrict__ ft) {
    int w    = (blockIdx.x * blockDim.x + threadIdx.x) >> 5;  // row
    int lane = threadIdx.x & 31;
    if (w >= N_ROWS) return;

    {
        float4 v = *(const float4*)(fs + (size_t)w * DIM + lane * 4);
        float ss = v.x * v.x + v.y * v.y + v.z * v.z + v.w * v.w;
        #pragma unroll
        for (int s = 16; s; s >>= 1) ss += __shfl_xor_sync(0xffffffffu, ss, s);
        float inv = 1.0f / fmaxf(sqrtf(ss), 1e-12f);
        float4 o = make_float4(v.x * inv, v.y * inv, v.z * inv, v.w * inv);
        *(float4*)(g_f1 + (size_t)w * DIM + lane * 4) = o;
    }
    {
        float4 v = *(const float4*)(ft + (size_t)w * DIM + lane * 4);
        float ss = v.x * v.x + v.y * v.y + v.z * v.z + v.w * v.w;
        #pragma unroll
        for (int s = 16; s; s >>= 1) ss += __shfl_xor_sync(0xffffffffu, ss, s);
        float inv = 1.0f / fmaxf(sqrtf(ss), 1e-12f);
        float4 o = make_float4(v.x * inv, v.y * inv, v.z * inv, v.w * inv);
        *(float4*)(g_f2 + (size_t)w * DIM + lane * 4) = o;
    }
}

// ---------------- K2: moments GEMM -----------------------------------------
// Per row i: S1 = sum_j e_ij, S2 = sum e^2, S3 = sum e^3, e = exp((cos-1)*10).
// Block tile: 64 rows x 128 cols, BK=32, 256 threads, 4x8 thread tile.
// Grid (NCHUNK j-chunks, 128 row tiles); partials written without atomics.
#define BM 64
#define BN 128
#define BK 32
#define AST 68    // As stride (floats): k*68*4B is 16B aligned, 4-way store conflicts only
#define BST 132   // Bs stride

__global__ __launch_bounds__(256) void k_moments() {
    __shared__ float As[BK * AST];
    __shared__ float Bs[BK * BST];

    const int tid  = threadIdx.x;
    const int tx   = tid & 15;      // 16 col-groups
    const int ty   = tid >> 4;      // 16 row-groups (4 rows each)
    const int row0 = blockIdx.y * BM;
    const int jbase = blockIdx.x * (N_ROWS / NCHUNK);

    const int l_r = tid >> 3;       // 0..31  (loader row index)
    const int l_k = (tid & 7) * 4;  // 0..28  (loader k offset)

    float s1[4] = {0.f, 0.f, 0.f, 0.f};
    float s2[4] = {0.f, 0.f, 0.f, 0.f};
    float s3[4] = {0.f, 0.f, 0.f, 0.f};

    for (int jt = 0; jt < (N_ROWS / NCHUNK) / BN; jt++) {
        const int j0 = jbase + jt * BN;

        float acc[4][8];
        #pragma unroll
        for (int r = 0; r < 4; r++)
            #pragma unroll
            for (int c = 0; c < 8; c++) acc[r][c] = 0.f;

        for (int kk = 0; kk < DIM; kk += BK) {
            // --- load A tile (64 x 32), transposed store ---
            #pragma unroll
            for (int p = 0; p < 2; p++) {
                int r = l_r + p * 32;
                float4 v = *(const float4*)(g_f1 + (size_t)(row0 + r) * DIM + kk + l_k);
                As[(l_k + 0) * AST + r] = v.x;
                As[(l_k + 1) * AST + r] = v.y;
                As[(l_k + 2) * AST + r] = v.z;
                As[(l_k + 3) * AST + r] = v.w;
            }
            // --- load B tile (128 x 32), transposed store ---
            #pragma unroll
            for (int p = 0; p < 4; p++) {
                int jr = l_r + p * 32;
                float4 v = *(const float4*)(g_f2 + (size_t)(j0 + jr) * DIM + kk + l_k);
                Bs[(l_k + 0) * BST + jr] = v.x;
                Bs[(l_k + 1) * BST + jr] = v.y;
                Bs[(l_k + 2) * BST + jr] = v.z;
                Bs[(l_k + 3) * BST + jr] = v.w;
            }
            __syncthreads();

            #pragma unroll 8
            for (int k = 0; k < BK; k++) {
                float4 av  = *(const float4*)&As[k * AST + ty * 4];
                float4 bv0 = *(const float4*)&Bs[k * BST + tx * 4];
                float4 bv1 = *(const float4*)&Bs[k * BST + 64 + tx * 4];
                float a0 = av.x, a1 = av.y, a2 = av.z, a3 = av.w;
                float b[8] = {bv0.x, bv0.y, bv0.z, bv0.w,
                              bv1.x, bv1.y, bv1.z, bv1.w};
                #pragma unroll
                for (int c = 0; c < 8; c++) {
                    acc[0][c] = fmaf(a0, b[c], acc[0][c]);
                    acc[1][c] = fmaf(a1, b[c], acc[1][c]);
                    acc[2][c] = fmaf(a2, b[c], acc[2][c]);
                    acc[3][c] = fmaf(a3, b[c], acc[3][c]);
                }
            }
            __syncthreads();
        }

        // --- fused epilogue: accumulate exp moments per row ---
        #pragma unroll
        for (int r = 0; r < 4; r++) {
            #pragma unroll
            for (int c = 0; c < 8; c++) {
                float e  = __expf((acc[r][c] - 1.0f) * 10.0f);
                float e2 = e * e;
                s1[r] += e;
                s2[r] += e2;
                s3[r] += e2 * e;
            }
        }
    }

    // reduce across the 16 tx threads that share each row (lanes 0..15 / 16..31)
    #pragma unroll
    for (int r = 0; r < 4; r++) {
        #pragma unroll
        for (int s = 8; s; s >>= 1) {
            s1[r] += __shfl_xor_sync(0xffffffffu, s1[r], s);
            s2[r] += __shfl_xor_sync(0xffffffffu, s2[r], s);
            s3[r] += __shfl_xor_sync(0xffffffffu, s3[r], s);
        }
    }
    if (tx == 0) {
        #pragma unroll
        for (int r = 0; r < 4; r++) {
            int row  = row0 + ty * 4 + r;
            int base = (blockIdx.x * N_ROWS + row) * 3;
            g_part[base + 0] = s1[r];
            g_part[base + 1] = s2[r];
            g_part[base + 2] = s3[r];
        }
    }
}

// ---------------- K3: combine chunk partials (deterministic order) ----------
__global__ void k_combine() {
    int i = blockIdx.x * blockDim.x + threadIdx.x;
    if (i >= N_ROWS) return;
    float a = 0.f, b = 0.f, c = 0.f;
    #pragma unroll
    for (int ch = 0; ch < NCHUNK; ch++) {
        int base = (ch * N_ROWS + i) * 3;
        a += g_part[base + 0];
        b += g_part[base + 1];
        c += g_part[base + 2];
    }
    g_S[i * 3 + 0] = a;
    g_S[i * 3 + 1] = b;
    g_S[i * 3 + 2] = c;
}

// ---------------- K4: positive pairs (warp per row, ballot scan) ------------
__global__ void k_pos(const long long* __restrict__ tgt) {
    int w    = (blockIdx.x * blockDim.x + threadIdx.x) >> 5;
    int lane = threadIdx.x & 31;
    if (w >= N_ROWS) return;

    long long ci = tgt[w];
    float4 a = *(const float4*)(g_f1 + (size_t)w * DIM + lane * 4);
    float invS1 = 1.0f / g_S[w * 3 + 0];

    float L = 0.f, P1 = 0.f, P2 = 0.f, P3 = 0.f;
    int np = 0;

    for (int jb = 0; jb < N_ROWS; jb += 32) {
        bool m = (tgt[jb + lane] == ci);
        unsigned msk = __ballot_sync(0xffffffffu, m);
        np += __popc(msk);
        while (msk) {
            int src = __ffs(msk) - 1;
            msk &= msk - 1;
            int j = jb + src;
            float4 b = *(const float4*)(g_f2 + (size_t)j * DIM + lane * 4);
            float d = a.x * b.x + a.y * b.y + a.z * b.z + a.w * b.w;
            #pragma unroll
            for (int s = 16; s; s >>= 1) d += __shfl_xor_sync(0xffffffffu, d, s);
            float e  = __expf((d - 1.0f) * 10.0f);
            float ps = e * invS1;
            L  -= __logf(ps + (float)EPSL);
            float p2 = ps * ps;
            P1 += ps;
            P2 += p2;
            P3 += p2 * ps;
        }
    }
    if (lane == 0) {
        g_pos[w * 4 + 0] = L;
        g_pos[w * 4 + 1] = P1;
        g_pos[w * 4 + 2] = P2;
        g_pos[w * 4 + 3] = P3;
        g_npos[w] = np;
    }
}

// ---------------- block reduce helper (256 threads) -------------------------
__device__ __forceinline__ float block_reduce(float v, int ismax, float* sh) {
    int lane = threadIdx.x & 31;
    int wid  = threadIdx.x >> 5;
    #pragma unroll
    for (int s = 16; s; s >>= 1) {
        float o = __shfl_xor_sync(0xffffffffu, v, s);
        v = ismax ? fmaxf(v, o) : (v + o);
    }
    if (lane == 0) sh[wid] = v;
    __syncthreads();
    if (wid == 0) {
        v = (lane < 8) ? sh[lane] : (ismax ? -3.0e38f : 0.0f);
        #pragma unroll
        for (int s = 4; s; s >>= 1) {
            float o = __shfl_xor_sync(0xffffffffu, v, s);
            v = ismax ? fmaxf(v, o) : (v + o);
        }
        if (lane == 0) sh[0] = v;
    }
    __syncthreads();
    float r = sh[0];
    __syncthreads();
    return r;
}

// ---------------- K5: JSD per row (block per row) ---------------------------
__global__ void k_jsd(const float* __restrict__ ls, const float* __restrict__ lt) {
    int r = blockIdx.x;
    const float* zs = ls + (size_t)r * NCLS;
    const float* zt = lt + (size_t)r * NCLS;
    int tid = threadIdx.x;
    __shared__ float sh[8];

    float ms = -3.0e38f, mt = -3.0e38f;
    for (int c = tid; c < NCLS; c += 256) {
        ms = fmaxf(ms, zs[c]);
        mt = fmaxf(mt, zt[c]);
    }
    ms = block_reduce(ms, 1, sh);
    mt = block_reduce(mt, 1, sh);

    float Ss = 0.f, St = 0.f;
    for (int c = tid; c < NCLS; c += 256) {
        Ss += __expf(zs[c] - ms);
        St += __expf(zt[c] - mt);
    }
    Ss = block_reduce(Ss, 0, sh);
    St = block_reduce(St, 0, sh);

    float lse_s = ms + __logf(Ss);
    float lse_t = mt + __logf(St);

    // kl_st + kl_ts = sum (pt - ps) * (log_pt - log_ps)
    float acc = 0.f;
    for (int c = tid; c < NCLS; c += 256) {
        float dls = zs[c] - lse_s;
        float dlt = zt[c] - lse_t;
        acc += (__expf(dlt) - __expf(dls)) * (dlt - dls);
    }
    acc = block_reduce(acc, 0, sh);
    if (tid == 0) g_jsd[r] = acc;
}

// ---------------- K6: final scalar (double precision combine) ---------------
__global__ void k_final(float* __restrict__ out) {
    int tid = threadIdx.x;
    double nce = 0.0, jsd = 0.0;
    for (int i = tid; i < N_ROWS; i += 256) {
        double S1 = (double)g_S[i * 3 + 0];
        double S2 = (double)g_S[i * 3 + 1];
        double S3 = (double)g_S[i * 3 + 2];
        double L  = (double)g_pos[i * 4 + 0];
        double P1 = (double)g_pos[i * 4 + 1];
        double P2 = (double)g_pos[i * 4 + 2];
        double P3 = (double)g_pos[i * 4 + 3];
        int np    = g_npos[i];
        double nn = (double)(N_ROWS - np);

        double q1 = 1.0 - P1;                  // sum_neg ps
        double q2 = S2 / (S1 * S1) - P2;       // sum_neg ps^2
        double q3 = S3 / (S1 * S1 * S1) - P3;  // sum_neg ps^3
        // sum_neg -log(1 - (ps - EPS)) ~= sum t + t^2/2 + t^3/3, t = ps - EPS
        double neg = (q1 - nn * EPSL) + 0.5 * (q2 - 2.0 * EPSL * q1) + q3 * (1.0 / 3.0);

        nce += L / (double)np + neg / nn;
        jsd += (double)g_jsd[i];
    }
    __shared__ double shn[256];
    __shared__ double shj[256];
    shn[tid] = nce;
    shj[tid] = jsd;
    __syncthreads();
    for (int s = 128; s; s >>= 1) {
        if (tid < s) {
            shn[tid] += shn[tid + s];
            shj[tid] += shj[tid + s];
        }
        __syncthreads();
    }
    if (tid == 0)
        out[0] = (float)(shn[0] / (double)N_ROWS + 0.5 * shj[0] / (double)N_ROWS);
}

// ---------------- launch -----------------------------------------------------
extern "C" void kernel_launch(void* const* d_in, const int* in_sizes, int n_in,
                              void* d_out, int out_size) {
    const float*     fs  = (const float*)d_in[0];
    const float*     ft  = (const float*)d_in[1];
    const float*     ls  = (const float*)d_in[2];
    const float*     lt  = (const float*)d_in[3];
    const long long* tgt = (const long long*)d_in[4];

    k_normalize<<<N_ROWS / 8, 256>>>(fs, ft);
    k_moments<<<dim3(NCHUNK, N_ROWS / BM), 256>>>();
    k_combine<<<N_ROWS / 256, 256>>>();
    k_pos<<<N_ROWS / 8, 256>>>(tgt);
    k_jsd<<<N_ROWS, 256>>>(ls, lt);
    k_final<<<1, 256>>>((float*)d_out);
}

// round 6
// speedup vs baseline: 1.0503x; 1.0503x over previous
#include <cuda_runtime.h>
#include <math.h>

// ---------------- problem constants ----------------
#define N_ROWS 8192
#define DIM    128
#define NCLS   1000
#define EPSL   1e-10
// NCE temperature 0.1 -> multiply shifted cos by 10

// ---------------- scratch (device globals; no allocations allowed) ----------
__device__ float g_f1[N_ROWS * DIM];   // normalized fs
__device__ float g_f2[N_ROWS * DIM];   // normalized ft

#define NCHUNK 4
__device__ float g_part[NCHUNK * N_ROWS * 3];  // per-chunk (S1,S2,S3) partials
__device__ float g_S[N_ROWS * 3];              // combined S1,S2,S3 per row
__device__ float g_pos[N_ROWS * 4];            // L, P1, P2, P3 per row
__device__ int   g_npos[N_ROWS];
__device__ float g_jsd[N_ROWS];

// ---------------- K1: L2-normalize rows of fs, ft (warp per row) ------------
__global__ void k_normalize(const float* __restrict__ fs,
                            const float* __restrict__ ft) {
    int w    = (blockIdx.x * blockDim.x + threadIdx.x) >> 5;  // row
    int lane = threadIdx.x & 31;
    if (w >= N_ROWS) return;

    {
        float4 v = *(const float4*)(fs + (size_t)w * DIM + lane * 4);
        float ss = v.x * v.x + v.y * v.y + v.z * v.z + v.w * v.w;
        #pragma unroll
        for (int s = 16; s; s >>= 1) ss += __shfl_xor_sync(0xffffffffu, ss, s);
        float inv = 1.0f / fmaxf(sqrtf(ss), 1e-12f);
        float4 o = make_float4(v.x * inv, v.y * inv, v.z * inv, v.w * inv);
        *(float4*)(g_f1 + (size_t)w * DIM + lane * 4) = o;
    }
    {
        float4 v = *(const float4*)(ft + (size_t)w * DIM + lane * 4);
        float ss = v.x * v.x + v.y * v.y + v.z * v.z + v.w * v.w;
        #pragma unroll
        for (int s = 16; s; s >>= 1) ss += __shfl_xor_sync(0xffffffffu, ss, s);
        float inv = 1.0f / fmaxf(sqrtf(ss), 1e-12f);
        float4 o = make_float4(v.x * inv, v.y * inv, v.z * inv, v.w * inv);
        *(float4*)(g_f2 + (size_t)w * DIM + lane * 4) = o;
    }
}

// ---------------- K2: moments GEMM -----------------------------------------
// Per row i: S1 = sum_j e_ij, S2 = sum e^2, S3 = sum e^3, e = exp((cos-1)*10).
// Block tile: 64 rows x 128 cols, BK=32, 256 threads, 4x8 thread tile.
// Grid (NCHUNK j-chunks, 128 row tiles); partials written without atomics.
#define BM 64
#define BN 128
#define BK 32
#define AST 68    // As stride (floats): k*68*4B is 16B aligned, 4-way store conflicts only
#define BST 132   // Bs stride

__global__ __launch_bounds__(256) void k_moments() {
    __shared__ float As[BK * AST];
    __shared__ float Bs[BK * BST];

    const int tid  = threadIdx.x;
    const int tx   = tid & 15;      // 16 col-groups
    const int ty   = tid >> 4;      // 16 row-groups (4 rows each)
    const int row0 = blockIdx.y * BM;
    const int jbase = blockIdx.x * (N_ROWS / NCHUNK);

    const int l_r = tid >> 3;       // 0..31  (loader row index)
    const int l_k = (tid & 7) * 4;  // 0..28  (loader k offset)

    float s1[4] = {0.f, 0.f, 0.f, 0.f};
    float s2[4] = {0.f, 0.f, 0.f, 0.f};
    float s3[4] = {0.f, 0.f, 0.f, 0.f};

    for (int jt = 0; jt < (N_ROWS / NCHUNK) / BN; jt++) {
        const int j0 = jbase + jt * BN;

        float acc[4][8];
        #pragma unroll
        for (int r = 0; r < 4; r++)
            #pragma unroll
            for (int c = 0; c < 8; c++) acc[r][c] = 0.f;

        for (int kk = 0; kk < DIM; kk += BK) {
            // --- load A tile (64 x 32), transposed store ---
            #pragma unroll
            for (int p = 0; p < 2; p++) {
                int r = l_r + p * 32;
                float4 v = *(const float4*)(g_f1 + (size_t)(row0 + r) * DIM + kk + l_k);
                As[(l_k + 0) * AST + r] = v.x;
                As[(l_k + 1) * AST + r] = v.y;
                As[(l_k + 2) * AST + r] = v.z;
                As[(l_k + 3) * AST + r] = v.w;
            }
            // --- load B tile (128 x 32), transposed store ---
            #pragma unroll
            for (int p = 0; p < 4; p++) {
                int jr = l_r + p * 32;
                float4 v = *(const float4*)(g_f2 + (size_t)(j0 + jr) * DIM + kk + l_k);
                Bs[(l_k + 0) * BST + jr] = v.x;
                Bs[(l_k + 1) * BST + jr] = v.y;
                Bs[(l_k + 2) * BST + jr] = v.z;
                Bs[(l_k + 3) * BST + jr] = v.w;
            }
            __syncthreads();

            #pragma unroll 8
            for (int k = 0; k < BK; k++) {
                float4 av  = *(const float4*)&As[k * AST + ty * 4];
                float4 bv0 = *(const float4*)&Bs[k * BST + tx * 4];
                float4 bv1 = *(const float4*)&Bs[k * BST + 64 + tx * 4];
                float a0 = av.x, a1 = av.y, a2 = av.z, a3 = av.w;
                float b[8] = {bv0.x, bv0.y, bv0.z, bv0.w,
                              bv1.x, bv1.y, bv1.z, bv1.w};
                #pragma unroll
                for (int c = 0; c < 8; c++) {
                    acc[0][c] = fmaf(a0, b[c], acc[0][c]);
                    acc[1][c] = fmaf(a1, b[c], acc[1][c]);
                    acc[2][c] = fmaf(a2, b[c], acc[2][c]);
                    acc[3][c] = fmaf(a3, b[c], acc[3][c]);
                }
            }
            __syncthreads();
        }

        // --- fused epilogue: accumulate exp moments per row ---
        #pragma unroll
        for (int r = 0; r < 4; r++) {
            #pragma unroll
            for (int c = 0; c < 8; c++) {
                float e  = __expf((acc[r][c] - 1.0f) * 10.0f);
                float e2 = e * e;
                s1[r] += e;
                s2[r] += e2;
                s3[r] += e2 * e;
            }
        }
    }

    // reduce across the 16 tx threads that share each row (lanes 0..15 / 16..31)
    #pragma unroll
    for (int r = 0; r < 4; r++) {
        #pragma unroll
        for (int s = 8; s; s >>= 1) {
            s1[r] += __shfl_xor_sync(0xffffffffu, s1[r], s);
            s2[r] += __shfl_xor_sync(0xffffffffu, s2[r], s);
            s3[r] += __shfl_xor_sync(0xffffffffu, s3[r], s);
        }
    }
    if (tx == 0) {
        #pragma unroll
        for (int r = 0; r < 4; r++) {
            int row  = row0 + ty * 4 + r;
            int base = (blockIdx.x * N_ROWS + row) * 3;
            g_part[base + 0] = s1[r];
            g_part[base + 1] = s2[r];
            g_part[base + 2] = s3[r];
        }
    }
}

// ---------------- K3: combine chunk partials (deterministic order) ----------
__global__ void k_combine() {
    int i = blockIdx.x * blockDim.x + threadIdx.x;
    if (i >= N_ROWS) return;
    float a = 0.f, b = 0.f, c = 0.f;
    #pragma unroll
    for (int ch = 0; ch < NCHUNK; ch++) {
        int base = (ch * N_ROWS + i) * 3;
        a += g_part[base + 0];
        b += g_part[base + 1];
        c += g_part[base + 2];
    }
    g_S[i * 3 + 0] = a;
    g_S[i * 3 + 1] = b;
    g_S[i * 3 + 2] = c;
}

// ---------------- K4: positive pairs (warp per row, ballot scan) ------------
__global__ void k_pos(const long long* __restrict__ tgt) {
    int w    = (blockIdx.x * blockDim.x + threadIdx.x) >> 5;
    int lane = threadIdx.x & 31;
    if (w >= N_ROWS) return;

    long long ci = tgt[w];
    float4 a = *(const float4*)(g_f1 + (size_t)w * DIM + lane * 4);
    float invS1 = 1.0f / g_S[w * 3 + 0];

    float L = 0.f, P1 = 0.f, P2 = 0.f, P3 = 0.f;
    int np = 0;

    for (int jb = 0; jb < N_ROWS; jb += 32) {
        bool m = (tgt[jb + lane] == ci);
        unsigned msk = __ballot_sync(0xffffffffu, m);
        np += __popc(msk);
        while (msk) {
            int src = __ffs(msk) - 1;
            msk &= msk - 1;
            int j = jb + src;
            float4 b = *(const float4*)(g_f2 + (size_t)j * DIM + lane * 4);
            float d = a.x * b.x + a.y * b.y + a.z * b.z + a.w * b.w;
            #pragma unroll
            for (int s = 16; s; s >>= 1) d += __shfl_xor_sync(0xffffffffu, d, s);
            float e  = __expf((d - 1.0f) * 10.0f);
            float ps = e * invS1;
            L  -= __logf(ps + (float)EPSL);
            float p2 = ps * ps;
            P1 += ps;
            P2 += p2;
            P3 += p2 * ps;
        }
    }
    if (lane == 0) {
        g_pos[w * 4 + 0] = L;
        g_pos[w * 4 + 1] = P1;
        g_pos[w * 4 + 2] = P2;
        g_pos[w * 4 + 3] = P3;
        g_npos[w] = np;
    }
}

// ---------------- block reduce helper (256 threads) -------------------------
__device__ __forceinline__ float block_reduce(float v, int ismax, float* sh) {
    int lane = threadIdx.x & 31;
    int wid  = threadIdx.x >> 5;
    #pragma unroll
    for (int s = 16; s; s >>= 1) {
        float o = __shfl_xor_sync(0xffffffffu, v, s);
        v = ismax ? fmaxf(v, o) : (v + o);
    }
    if (lane == 0) sh[wid] = v;
    __syncthreads();
    if (wid == 0) {
        v = (lane < 8) ? sh[lane] : (ismax ? -3.0e38f : 0.0f);
        #pragma unroll
        for (int s = 4; s; s >>= 1) {
            float o = __shfl_xor_sync(0xffffffffu, v, s);
            v = ismax ? fmaxf(v, o) : (v + o);
        }
        if (lane == 0) sh[0] = v;
    }
    __syncthreads();
    float r = sh[0];
    __syncthreads();
    return r;
}

// ---------------- K5: JSD per row (block per row) ---------------------------
__global__ void k_jsd(const float* __restrict__ ls, const float* __restrict__ lt) {
    int r = blockIdx.x;
    const float* zs = ls + (size_t)r * NCLS;
    const float* zt = lt + (size_t)r * NCLS;
    int tid = threadIdx.x;
    __shared__ float sh[8];

    float ms = -3.0e38f, mt = -3.0e38f;
    for (int c = tid; c < NCLS; c += 256) {
        ms = fmaxf(ms, zs[c]);
        mt = fmaxf(mt, zt[c]);
    }
    ms = block_reduce(ms, 1, sh);
    mt = block_reduce(mt, 1, sh);

    float Ss = 0.f, St = 0.f;
    for (int c = tid; c < NCLS; c += 256) {
        Ss += __expf(zs[c] - ms);
        St += __expf(zt[c] - mt);
    }
    Ss = block_reduce(Ss, 0, sh);
    St = block_reduce(St, 0, sh);

    float lse_s = ms + __logf(Ss);
    float lse_t = mt + __logf(St);

    // kl_st + kl_ts = sum (pt - ps) * (log_pt - log_ps)
    float acc = 0.f;
    for (int c = tid; c < NCLS; c += 256) {
        float dls = zs[c] - lse_s;
        float dlt = zt[c] - lse_t;
        acc += (__expf(dlt) - __expf(dls)) * (dlt - dls);
    }
    acc = block_reduce(acc, 0, sh);
    if (tid == 0) g_jsd[r] = acc;
}

// ---------------- K6: final scalar (double precision combine) ---------------
__global__ void k_final(float* __restrict__ out) {
    int tid = threadIdx.x;
    double nce = 0.0, jsd = 0.0;
    for (int i = tid; i < N_ROWS; i += 256) {
        double S1 = (double)g_S[i * 3 + 0];
        double S2 = (double)g_S[i * 3 + 1];
        double S3 = (double)g_S[i * 3 + 2];
        double L  = (double)g_pos[i * 4 + 0];
        double P1 = (double)g_pos[i * 4 + 1];
        double P2 = (double)g_pos[i * 4 + 2];
        double P3 = (double)g_pos[i * 4 + 3];
        int np    = g_npos[i];
        double nn = (double)(N_ROWS - np);

        double q1 = 1.0 - P1;                  // sum_neg ps
        double q2 = S2 / (S1 * S1) - P2;       // sum_neg ps^2
        double q3 = S3 / (S1 * S1 * S1) - P3;  // sum_neg ps^3
        // sum_neg -log(1 - (ps - EPS)) ~= sum t + t^2/2 + t^3/3, t = ps - EPS
        double neg = (q1 - nn * EPSL) + 0.5 * (q2 - 2.0 * EPSL * q1) + q3 * (1.0 / 3.0);

        nce += L / (double)np + neg / nn;
        jsd += (double)g_jsd[i];
    }
    __shared__ double shn[256];
    __shared__ double shj[256];
    shn[tid] = nce;
    shj[tid] = jsd;
    __syncthreads();
    for (int s = 128; s; s >>= 1) {
        if (tid < s) {
            shn[tid] += shn[tid + s];
            shj[tid] += shj[tid + s];
        }
        __syncthreads();
    }
    if (tid == 0)
        out[0] = (float)(shn[0] / (double)N_ROWS + 0.5 * shj[0] / (double)N_ROWS);
}

// ---------------- launch -----------------------------------------------------
extern "C" void kernel_launch(void* const* d_in, const int* in_sizes, int n_in,
                              void* d_out, int out_size) {
    const float*     fs  = (const float*)d_in[0];
    const float*     ft  = (const float*)d_in[1];
    const float*     ls  = (const float*)d_in[2];
    const float*     lt  = (const float*)d_in[3];
    const long long* tgt = (const long long*)d_in[4];

    k_normalize<<<N_ROWS / 8, 256>>>(fs, ft);
    k_moments<<<dim3(NCHUNK, N_ROWS / BM), 256>>>();
    k_combine<<<N_ROWS / 256, 256>>>();
    k_pos<<<N_ROWS / 8, 256>>>(tgt);
    k_jsd<<<N_ROWS, 256>>>(ls, lt);
    k_final<<<1, 256>>>((float*)d_out);
}

// round 8
// speedup vs baseline: 1.1855x; 1.1287x over previous
#include <cuda_runtime.h>
#include <cuda_bf16.h>
#include <math.h>
#include <stdint.h>

// ---------------- problem constants ----------------
#define N_ROWS 8192
#define DIM    128
#define NCLS   1000
#define EPSL   1e-10
#define NCHUNK 16               // j-chunks; 64/NCHUNK = 4 j-tiles per CTA
#define JT     (64 / NCHUNK)

// ---------------- scratch (device globals; no allocations) ------------------
__device__ __align__(16) float         g_f1[N_ROWS * DIM];   // normalized fs (fp32)
__device__ __align__(16) float         g_f2[N_ROWS * DIM];   // normalized ft (fp32)
__device__ __align__(16) __nv_bfloat16 g_hi1[N_ROWS * DIM];  // bf16 hi/lo splits, row-major
__device__ __align__(16) __nv_bfloat16 g_lo1[N_ROWS * DIM];
__device__ __align__(16) __nv_bfloat16 g_hi2[N_ROWS * DIM];
__device__ __align__(16) __nv_bfloat16 g_lo2[N_ROWS * DIM];

__device__ float g_part[NCHUNK * N_ROWS * 3];  // per-chunk (S1,S2,S3)
__device__ float g_S[N_ROWS * 3];
__device__ float g_pos[N_ROWS * 4];            // L, P1, P2, P3
__device__ int   g_npos[N_ROWS];
__device__ float g_jsd[N_ROWS];

// ---------------- PTX helpers -----------------------------------------------
__device__ __forceinline__ uint32_t smem_u32(const void* p) {
    uint32_t a;
    asm("{ .reg .u64 t; cvta.to.shared.u64 t, %1; cvt.u32.u64 %0, t; }"
        : "=r"(a) : "l"(p));
    return a;
}
__device__ __forceinline__ void cpa16(uint32_t s, const void* g) {
    asm volatile("cp.async.cg.shared.global [%0], [%1], 16;"
                 :: "r"(s), "l"(g) : "memory");
}
__device__ __forceinline__ void cpa_commit() {
    asm volatile("cp.async.commit_group;" ::: "memory");
}
__device__ __forceinline__ void cpa_wait0() {
    asm volatile("cp.async.wait_group 0;" ::: "memory");
}
__device__ __forceinline__ uint32_t lds32(uint32_t a) {
    uint32_t v;
    asm volatile("ld.shared.b32 %0, [%1];" : "=r"(v) : "r"(a));
    return v;
}
__device__ __forceinline__ void mma16816(float c[4], const uint32_t a[4],
                                         const uint32_t b[2]) {
    asm volatile(
        "mma.sync.aligned.m16n8k16.row.col.f32.bf16.bf16.f32 "
        "{%0,%1,%2,%3}, {%4,%5,%6,%7}, {%8,%9}, {%0,%1,%2,%3};"
        : "+f"(c[0]), "+f"(c[1]), "+f"(c[2]), "+f"(c[3])
        : "r"(a[0]), "r"(a[1]), "r"(a[2]), "r"(a[3]), "r"(b[0]), "r"(b[1]));
}

// ---------------- K1: normalize + bf16 hi/lo split ---------------------------
__device__ __forceinline__ void norm_one(const float* __restrict__ in,
                                         float* __restrict__ fout,
                                         __nv_bfloat16* hi, __nv_bfloat16* lo,
                                         int w, int lane) {
    float4 v = *(const float4*)(in + (size_t)w * DIM + lane * 4);
    float ss = v.x * v.x + v.y * v.y + v.z * v.z + v.w * v.w;
    #pragma unroll
    for (int s = 16; s; s >>= 1) ss += __shfl_xor_sync(0xffffffffu, ss, s);
    float inv = 1.0f / fmaxf(sqrtf(ss), 1e-12f);
    float x[4] = {v.x * inv, v.y * inv, v.z * inv, v.w * inv};
    *(float4*)(fout + (size_t)w * DIM + lane * 4) = make_float4(x[0], x[1], x[2], x[3]);

    uint32_t ph[2] = {0, 0}, pl[2] = {0, 0};
    #pragma unroll
    for (int i = 0; i < 4; i++) {
        __nv_bfloat16 h = __float2bfloat16(x[i]);
        __nv_bfloat16 l = __float2bfloat16(x[i] - __bfloat162float(h));
        ph[i >> 1] |= (uint32_t)__bfloat16_as_ushort(h) << (16 * (i & 1));
        pl[i >> 1] |= (uint32_t)__bfloat16_as_ushort(l) << (16 * (i & 1));
    }
    size_t base = (size_t)w * DIM + lane * 4;  // elements
    *(uint2*)((char*)hi + base * 2) = make_uint2(ph[0], ph[1]);
    *(uint2*)((char*)lo + base * 2) = make_uint2(pl[0], pl[1]);
}

__global__ void k_normalize(const float* __restrict__ fs,
                            const float* __restrict__ ft) {
    int w    = (blockIdx.x * blockDim.x + threadIdx.x) >> 5;
    int lane = threadIdx.x & 31;
    if (w >= N_ROWS) return;
    norm_one(fs, g_f1, g_hi1, g_lo1, w, lane);
    norm_one(ft, g_f2, g_hi2, g_lo2, w, lane);
}

// ---------------- K2: mma.sync bf16 hi/lo moments GEMM -----------------------
// SMEM tile layout: 16 column-chunks of 16B per row, chunk stride 2064 bytes
// (129*16: conflict-free for both cp.async stores and fragment LDS).
// Buffers: A_hi, A_lo, B_hi[2], B_lo[2] (B double-buffered).
#define BUF_B  33024                     // 16 * 2064
#define SM_AHI 0
#define SM_ALO BUF_B
#define SM_B(s) (2 * BUF_B + (s) * 2 * BUF_B)   // hi at +0, lo at +BUF_B
#define SMEM_GEMM (6 * BUF_B)            // 198144 bytes

// copy one 128x128 bf16 tile (row-major global, 256B/row) into chunked smem
__device__ __forceinline__ void load_tile(uint32_t sdst, const char* gsrc, int tid) {
    #pragma unroll
    for (int i = 0; i < 4; i++) {
        int flat = tid + i * 512;
        int r = flat >> 4, gI = flat & 15;
        cpa16(sdst + gI * 2064 + r * 16, gsrc + r * 256 + gI * 16);
    }
}

__global__ __launch_bounds__(512) void k_moments_mma() {
    extern __shared__ __align__(16) char smem[];
    const int tid  = threadIdx.x;
    const int warp = tid >> 5, lane = tid & 31;
    const int g    = lane >> 2, tg = lane & 3;
    const int wm   = warp >> 2, wn = warp & 3;
    const int row0 = blockIdx.y * 128;
    const int chunk = blockIdx.x;

    const uint32_t sb = smem_u32(smem);

    // ---- initial loads: A (both) + B stage 0 ----
    const char* Ahi_g = (const char*)g_hi1 + (size_t)row0 * 256;
    const char* Alo_g = (const char*)g_lo1 + (size_t)row0 * 256;
    {
        int t0 = chunk * JT;
        load_tile(sb + SM_AHI, Ahi_g, tid);
        load_tile(sb + SM_ALO, Alo_g, tid);
        load_tile(sb + SM_B(0),         (const char*)g_hi2 + (size_t)t0 * 32768, tid);
        load_tile(sb + SM_B(0) + BUF_B, (const char*)g_lo2 + (size_t)t0 * 32768, tid);
        cpa_commit();
        cpa_wait0();
    }
    __syncthreads();

    // per-thread fragment byte offsets within a buffer (chunk 0)
    const uint32_t aByte = (uint32_t)(wm * 32 + g) * 16 + tg * 4;
    const uint32_t bByte = (uint32_t)(wn * 32 + g) * 16 + tg * 4;

    float s1[4] = {0, 0, 0, 0}, s2[4] = {0, 0, 0, 0}, s3[4] = {0, 0, 0, 0};

    for (int jt = 0; jt < JT; jt++) {
        const int cur = jt & 1;
        if (jt + 1 < JT) {
            int tn = chunk * JT + jt + 1;
            load_tile(sb + SM_B(1 - cur),         (const char*)g_hi2 + (size_t)tn * 32768, tid);
            load_tile(sb + SM_B(1 - cur) + BUF_B, (const char*)g_lo2 + (size_t)tn * 32768, tid);
            cpa_commit();
        }

        float cacc[2][4][4];
        #pragma unroll
        for (int mt = 0; mt < 2; mt++)
            #pragma unroll
            for (int nt = 0; nt < 4; nt++)
                #pragma unroll
                for (int ci = 0; ci < 4; ci++) cacc[mt][nt][ci] = 0.f;

        const uint32_t aHi = sb + SM_AHI + aByte;
        const uint32_t aLo = sb + SM_ALO + aByte;
        const uint32_t bHi = sb + SM_B(cur) + bByte;
        const uint32_t bLo = bHi + BUF_B;

        #pragma unroll
        for (int ks = 0; ks < 8; ks++) {
            const uint32_t c0 = (uint32_t)(2 * ks) * 2064, c1 = c0 + 2064;
            uint32_t ahf[2][4], alf[2][4], bhf[4][2], blf[4][2];
            #pragma unroll
            for (int mt = 0; mt < 2; mt++) {
                uint32_t ro = mt * 256;
                ahf[mt][0] = lds32(aHi + c0 + ro);
                ahf[mt][1] = lds32(aHi + c0 + ro + 128);
                ahf[mt][2] = lds32(aHi + c1 + ro);
                ahf[mt][3] = lds32(aHi + c1 + ro + 128);
                alf[mt][0] = lds32(aLo + c0 + ro);
                alf[mt][1] = lds32(aLo + c0 + ro + 128);
                alf[mt][2] = lds32(aLo + c1 + ro);
                alf[mt][3] = lds32(aLo + c1 + ro + 128);
            }
            #pragma unroll
            for (int nt = 0; nt < 4; nt++) {
                uint32_t no = nt * 128;
                bhf[nt][0] = lds32(bHi + c0 + no);
                bhf[nt][1] = lds32(bHi + c1 + no);
                blf[nt][0] = lds32(bLo + c0 + no);
                blf[nt][1] = lds32(bLo + c1 + no);
            }
            #pragma unroll
            for (int mt = 0; mt < 2; mt++)
                #pragma unroll
                for (int nt = 0; nt < 4; nt++) {
                    mma16816(cacc[mt][nt], ahf[mt], bhf[nt]);
                    mma16816(cacc[mt][nt], ahf[mt], blf[nt]);
                    mma16816(cacc[mt][nt], alf[mt], bhf[nt]);
                }
        }

        // fused epilogue: moments per row-slot (slot = mt*2 + (ci>>1))
        #pragma unroll
        for (int mt = 0; mt < 2; mt++)
            #pragma unroll
            for (int nt = 0; nt < 4; nt++)
                #pragma unroll
                for (int ci = 0; ci < 4; ci++) {
                    int slot = mt * 2 + (ci >> 1);
                    float e  = __expf((cacc[mt][nt][ci] - 1.0f) * 10.0f);
                    float e2 = e * e;
                    s1[slot] += e;
                    s2[slot] += e2;
                    s3[slot] += e2 * e;
                }

        if (jt + 1 < JT) cpa_wait0();
        __syncthreads();
    }

    // ---- reduction: quad (tg) shuffle, then cross-n-warp via smem ----
    #pragma unroll
    for (int slot = 0; slot < 4; slot++) {
        #pragma unroll
        for (int s = 1; s <= 2; s <<= 1) {
            s1[slot] += __shfl_xor_sync(0xffffffffu, s1[slot], s);
            s2[slot] += __shfl_xor_sync(0xffffffffu, s2[slot], s);
            s3[slot] += __shfl_xor_sync(0xffffffffu, s3[slot], s);
        }
    }
    float* red = (float*)smem;  // 4 nwarps * 128 rows * 3 = 6 KB, reuses A buffer
    if (tg == 0) {
        #pragma unroll
        for (int slot = 0; slot < 4; slot++) {
            int row = wm * 32 + (slot >> 1) * 16 + (slot & 1) * 8 + g;
            int idx = wn * 384 + row * 3;
            red[idx + 0] = s1[slot];
            red[idx + 1] = s2[slot];
            red[idx + 2] = s3[slot];
        }
    }
    __syncthreads();
    if (tid < 384) {
        int row = tid / 3, m = tid - row * 3;
        float v = red[row * 3 + m] + red[384 + row * 3 + m] +
                  red[768 + row * 3 + m] + red[1152 + row * 3 + m];
        g_part[((size_t)chunk * N_ROWS + row0 + row) * 3 + m] = v;
    }
}

// ---------------- K3: combine chunk partials --------------------------------
__global__ void k_combine() {
    int i = blockIdx.x * blockDim.x + threadIdx.x;
    if (i >= N_ROWS) return;
    float a = 0.f, b = 0.f, c = 0.f;
    #pragma unroll
    for (int ch = 0; ch < NCHUNK; ch++) {
        int base = (ch * N_ROWS + i) * 3;
        a += g_part[base + 0];
        b += g_part[base + 1];
        c += g_part[base + 2];
    }
    g_S[i * 3 + 0] = a;
    g_S[i * 3 + 1] = b;
    g_S[i * 3 + 2] = c;
}

// ---------------- K4: positive pairs (warp per row) -------------------------
__global__ void k_pos(const long long* __restrict__ tgt) {
    int w    = (blockIdx.x * blockDim.x + threadIdx.x) >> 5;
    int lane = threadIdx.x & 31;
    if (w >= N_ROWS) return;

    long long ci = tgt[w];
    float4 a = *(const float4*)(g_f1 + (size_t)w * DIM + lane * 4);
    float invS1 = 1.0f / g_S[w * 3 + 0];

    float L = 0.f, P1 = 0.f, P2 = 0.f, P3 = 0.f;
    int np = 0;
    for (int jb = 0; jb < N_ROWS; jb += 32) {
        unsigned msk = __ballot_sync(0xffffffffu, tgt[jb + lane] == ci);
        np += __popc(msk);
        while (msk) {
            int j = jb + __ffs(msk) - 1;
            msk &= msk - 1;
            float4 b = *(const float4*)(g_f2 + (size_t)j * DIM + lane * 4);
            float d = a.x * b.x + a.y * b.y + a.z * b.z + a.w * b.w;
            #pragma unroll
            for (int s = 16; s; s >>= 1) d += __shfl_xor_sync(0xffffffffu, d, s);
            float e  = __expf((d - 1.0f) * 10.0f);
            float ps = e * invS1;
            L -= __logf(ps + (float)EPSL);
            float p2 = ps * ps;
            P1 += ps;
            P2 += p2;
            P3 += p2 * ps;
        }
    }
    if (lane == 0) {
        g_pos[w * 4 + 0] = L;
        g_pos[w * 4 + 1] = P1;
        g_pos[w * 4 + 2] = P2;
        g_pos[w * 4 + 3] = P3;
        g_npos[w] = np;
    }
}

// ---------------- block reduce helper ---------------------------------------
__device__ __forceinline__ float block_reduce(float v, int ismax, float* sh) {
    int lane = threadIdx.x & 31, wid = threadIdx.x >> 5;
    #pragma unroll
    for (int s = 16; s; s >>= 1) {
        float o = __shfl_xor_sync(0xffffffffu, v, s);
        v = ismax ? fmaxf(v, o) : (v + o);
    }
    if (lane == 0) sh[wid] = v;
    __syncthreads();
    if (wid == 0) {
        v = (lane < 8) ? sh[lane] : (ismax ? -3.0e38f : 0.0f);
        #pragma unroll
        for (int s = 4; s; s >>= 1) {
            float o = __shfl_xor_sync(0xffffffffu, v, s);
            v = ismax ? fmaxf(v, o) : (v + o);
        }
        if (lane == 0) sh[0] = v;
    }
    __syncthreads();
    float r = sh[0];
    __syncthreads();
    return r;
}

// ---------------- K5: JSD per row -------------------------------------------
__global__ void k_jsd(const float* __restrict__ ls, const float* __restrict__ lt) {
    int r = blockIdx.x;
    const float* zs = ls + (size_t)r * NCLS;
    const float* zt = lt + (size_t)r * NCLS;
    int tid = threadIdx.x;
    __shared__ float sh[8];

    float ms = -3.0e38f, mt = -3.0e38f;
    for (int c = tid; c < NCLS; c += 256) {
        ms = fmaxf(ms, zs[c]);
        mt = fmaxf(mt, zt[c]);
    }
    ms = block_reduce(ms, 1, sh);
    mt = block_reduce(mt, 1, sh);

    float Ss = 0.f, St = 0.f;
    for (int c = tid; c < NCLS; c += 256) {
        Ss += __expf(zs[c] - ms);
        St += __expf(zt[c] - mt);
    }
    Ss = block_reduce(Ss, 0, sh);
    St = block_reduce(St, 0, sh);

    float lse_s = ms + __logf(Ss);
    float lse_t = mt + __logf(St);

    float acc = 0.f;
    for (int c = tid; c < NCLS; c += 256) {
        float dls = zs[c] - lse_s;
        float dlt = zt[c] - lse_t;
        acc += (__expf(dlt) - __expf(dls)) * (dlt - dls);
    }
    acc = block_reduce(acc, 0, sh);
    if (tid == 0) g_jsd[r] = acc;
}

// ---------------- K6: final scalar (double precision combine) ---------------
__global__ void k_final(float* __restrict__ out) {
    int tid = threadIdx.x;
    double nce = 0.0, jsd = 0.0;
    for (int i = tid; i < N_ROWS; i += 256) {
        double S1 = (double)g_S[i * 3 + 0];
        double S2 = (double)g_S[i * 3 + 1];
        double S3 = (double)g_S[i * 3 + 2];
        double L  = (double)g_pos[i * 4 + 0];
        double P1 = (double)g_pos[i * 4 + 1];
        double P2 = (double)g_pos[i * 4 + 2];
        double P3 = (double)g_pos[i * 4 + 3];
        int np    = g_npos[i];
        double nn = (double)(N_ROWS - np);

        double q1 = 1.0 - P1;
        double q2 = S2 / (S1 * S1) - P2;
        double q3 = S3 / (S1 * S1 * S1) - P3;
        double neg = (q1 - nn * EPSL) + 0.5 * (q2 - 2.0 * EPSL * q1) + q3 * (1.0 / 3.0);

        nce += L / (double)np + neg / nn;
        jsd += (double)g_jsd[i];
    }
    __shared__ double shn[256], shj[256];
    shn[tid] = nce;
    shj[tid] = jsd;
    __syncthreads();
    for (int s = 128; s; s >>= 1) {
        if (tid < s) { shn[tid] += shn[tid + s]; shj[tid] += shj[tid + s]; }
        __syncthreads();
    }
    if (tid == 0)
        out[0] = (float)(shn[0] / (double)N_ROWS + 0.5 * shj[0] / (double)N_ROWS);
}

// ---------------- launch ------------------------------------------------------
extern "C" void kernel_launch(void* const* d_in, const int* in_sizes, int n_in,
                              void* d_out, int out_size) {
    const float*     fs  = (const float*)d_in[0];
    const float*     ft  = (const float*)d_in[1];
    const float*     ls  = (const float*)d_in[2];
    const float*     lt  = (const float*)d_in[3];
    const long long* tgt = (const long long*)d_in[4];

    cudaFuncSetAttribute(k_moments_mma,
                         cudaFuncAttributeMaxDynamicSharedMemorySize, SMEM_GEMM);

    k_normalize<<<N_ROWS / 8, 256>>>(fs, ft);
    k_moments_mma<<<dim3(NCHUNK, N_ROWS / 128), 512, SMEM_GEMM>>>();
    k_combine<<<N_ROWS / 256, 256>>>();
    k_pos<<<N_ROWS / 8, 256>>>(tgt);
    k_jsd<<<N_ROWS, 256>>>(ls, lt);
    k_final<<<1, 256>>>((float*)d_out);
}